// round 14
// baseline (speedup 1.0000x reference)
#include <cuda_runtime.h>
#include <cuda_fp16.h>
#include <math.h>
#include <stdint.h>

// Problem sizes
#define NB 2048
#define ND 64
#define NL 64
#define NH 512
#define MR 32                 // rows per CTA (half a batch element)

// SMEM layout (in halves)
#define ZSTRIDE 72            // 64 + 8 pad -> conflict-free ldmatrix
#define HSTRIDE 520           // 512 + 8 pad
#define BUF0_OFF (MR * ZSTRIDE)
#define BUF1_OFF (BUF0_OFF + MR * HSTRIDE)
#define SMEM_HALVES (BUF1_OFF + MR * HSTRIDE)
// after halves: partsm_s[8*32] f32, partsm_t[8*32] f32
#define SMEM_BYTES (SMEM_HALVES * 2 + 16 * MR * 4 + 16)

// Fragment-major fp16 weights, PAIR-PACKED for LDG.128 (same layout as r12):
__device__ __half2 g_Wf1[2][NL * NH / 2];   // Ks = 4
__device__ __half2 g_Wf2[2][NH * NH / 2];   // Ks = 32
__device__ __half2 g_Wf3[2][NH * NH / 2];   // Ks = 32
// W4 packed to match mma accumulator layout:
// j = ((((w*4+rt)*8+nt)*2+p)*32+lane); half2(W4[n0][r], W4[n0+1][r]),
// n0 = w*64+nt*8+(lane&3)*2, r = rt*16+(lane>>2)+p*8   (rt GLOBAL 0..3, w 0..7)
__device__ __half2 g_W4f[2][ND * NH / 2];

__global__ void convert_kernel(const float* __restrict__ sW1, const float* __restrict__ sW2,
                               const float* __restrict__ sW3, const float* __restrict__ sW4,
                               const float* __restrict__ tW1, const float* __restrict__ tW2,
                               const float* __restrict__ tW3, const float* __restrict__ tW4) {
    const int i = blockIdx.x * blockDim.x + threadIdx.x;
    const float* w1[2] = {sW1, tW1};
    const float* w2[2] = {sW2, tW2};
    const float* w3[2] = {sW3, tW3};
    const float* w4[2] = {sW4, tW4};
#pragma unroll
    for (int m = 0; m < 2; m++) {
        if (i < NH * NH / 2) {   // W2/W3: Ks = 32, Ks2 = 16
            const int c = i & 3, w = c & 1, sub = c >> 1;
            const int lane = (i >> 2) & 31, ks2 = (i >> 7) & 15, n8 = i >> 11;
            const int kstep = ks2 * 2 + sub;
            const int n = n8 * 8 + (lane >> 2);
            const int k = kstep * 16 + (lane & 3) * 2 + w * 8;
            g_Wf2[m][i] = __floats2half2_rn(w2[m][k * NH + n], w2[m][(k + 1) * NH + n]);
            g_Wf3[m][i] = __floats2half2_rn(w3[m][k * NH + n], w3[m][(k + 1) * NH + n]);
        }
        if (i < NL * NH / 2) {   // W1: Ks = 4, Ks2 = 2
            const int c = i & 3, w = c & 1, sub = c >> 1;
            const int lane = (i >> 2) & 31, ks2 = (i >> 7) & 1, n8 = i >> 8;
            const int kstep = ks2 * 2 + sub;
            const int n = n8 * 8 + (lane >> 2);
            const int k = kstep * 16 + (lane & 3) * 2 + w * 8;
            g_Wf1[m][i] = __floats2half2_rn(w1[m][k * NH + n], w1[m][(k + 1) * NH + n]);
        }
        if (i < ND * NH / 2) {   // W4 (512,64) -> accumulator-matched fragments
            const int lane = i & 31, p = (i >> 5) & 1, nt = (i >> 6) & 7;
            const int rt = (i >> 9) & 3, w = i >> 11;
            const int tg = lane & 3, g = lane >> 2;
            const int n0 = w * 64 + nt * 8 + tg * 2;
            const int r = rt * 16 + g + p * 8;
            g_W4f[m][i] = __floats2half2_rn(w4[m][n0 * ND + r], w4[m][(n0 + 1) * ND + r]);
        }
    }
}

__device__ __forceinline__ float tanh_approx(float x) {
    float y;
    asm("tanh.approx.f32 %0, %1;" : "=f"(y) : "f"(x));
    return y;
}

__device__ __forceinline__ void mma_m16n8k16(float c[4], const uint32_t a[4],
                                             uint32_t b0, uint32_t b1) {
    asm volatile(
        "mma.sync.aligned.m16n8k16.row.col.f32.f16.f16.f32 "
        "{%0,%1,%2,%3}, {%4,%5,%6,%7}, {%8,%9}, {%0,%1,%2,%3};\n"
        : "+f"(c[0]), "+f"(c[1]), "+f"(c[2]), "+f"(c[3])
        : "r"(a[0]), "r"(a[1]), "r"(a[2]), "r"(a[3]), "r"(b0), "r"(b1));
}

__device__ __forceinline__ void ldsm4(uint32_t a[4], uint32_t addr) {
    asm volatile("ldmatrix.sync.aligned.m8n8.x4.shared.b16 {%0,%1,%2,%3}, [%4];"
                 : "=r"(a[0]), "=r"(a[1]), "=r"(a[2]), "=r"(a[3]) : "r"(addr));
}

// One dense layer: Out(32 x 512) = tanh(A(32 x K) @ W(K x 512) + bias)
// 8 warps; warp w owns output columns [w*64, w*64+64); 2 row tiles (M=32).
// B reloads are spread: bc[nt] for next k-step reloads right after last use.
template <int K, int AS>
__device__ __noinline__ void mlp_layer(const __half* __restrict__ A,
                                       const __half2* __restrict__ Wf,
                                       const float* __restrict__ bias,
                                       __half* __restrict__ Out) {
    constexpr int Ks = K / 16;
    constexpr int Ks2 = Ks / 2;
    const int lane = threadIdx.x & 31;
    const int warp = threadIdx.x >> 5;
    const int g = lane >> 2;
    const int tg = lane & 3;
    const int ncol0 = warp * 64;

    uint32_t abase[2];
    {
        const __half* ap = A + (lane & 15) * AS + ((lane >> 4) << 3);
#pragma unroll
        for (int rt = 0; rt < 2; rt++)
            abase[rt] = (uint32_t)__cvta_generic_to_shared(ap + rt * 16 * AS);
    }

    const uint4* bq = reinterpret_cast<const uint4*>(Wf) + (warp * 8) * (Ks2 * 32) + lane;

    float c[2][8][4];
#pragma unroll
    for (int rt = 0; rt < 2; rt++)
#pragma unroll
        for (int nt = 0; nt < 8; nt++)
#pragma unroll
            for (int r = 0; r < 4; r++) c[rt][nt][r] = 0.f;

    uint4 bc[8];
#pragma unroll
    for (int nt = 0; nt < 8; nt++) bc[nt] = bq[nt * (Ks2 * 32)];

#pragma unroll 2
    for (int ks2 = 0; ks2 < Ks2; ks2++) {
        uint32_t a[2][4];
        ldsm4(a[0], abase[0] + (ks2 * 2) * 32);
        ldsm4(a[1], abase[1] + (ks2 * 2) * 32);
#pragma unroll
        for (int rt = 0; rt < 2; rt++)
#pragma unroll
            for (int nt = 0; nt < 8; nt++)
                mma_m16n8k16(c[rt][nt], a[rt], bc[nt].x, bc[nt].y);

        ldsm4(a[0], abase[0] + (ks2 * 2 + 1) * 32);
        ldsm4(a[1], abase[1] + (ks2 * 2 + 1) * 32);
#pragma unroll
        for (int nt = 0; nt < 8; nt++) {
            mma_m16n8k16(c[0][nt], a[0], bc[nt].z, bc[nt].w);
            mma_m16n8k16(c[1][nt], a[1], bc[nt].z, bc[nt].w);
            if (ks2 + 1 < Ks2)          // spread reload right after last use
                bc[nt] = bq[nt * (Ks2 * 32) + (ks2 + 1) * 32];
        }
    }

    // epilogue: + bias, tanh, pack to half2, store
#pragma unroll
    for (int nt = 0; nt < 8; nt++) {
        const int n0 = ncol0 + nt * 8 + tg * 2;
        const float2 bb = *reinterpret_cast<const float2*>(bias + n0);
#pragma unroll
        for (int rt = 0; rt < 2; rt++) {
            float v0 = tanh_approx(c[rt][nt][0] + bb.x);
            float v1 = tanh_approx(c[rt][nt][1] + bb.y);
            float v2 = tanh_approx(c[rt][nt][2] + bb.x);
            float v3 = tanh_approx(c[rt][nt][3] + bb.y);
            *reinterpret_cast<__half2*>(Out + (rt * 16 + g) * HSTRIDE + n0) =
                __floats2half2_rn(v0, v1);
            *reinterpret_cast<__half2*>(Out + (rt * 16 + g + 8) * HSTRIDE + n0) =
                __floats2half2_rn(v2, v3);
        }
    }
}

// Layer 3 fused with the layer-4 diagonal (M=32; global row = half*32 + local).
__device__ __noinline__ void mlp_layer_diag(const __half* __restrict__ A,
                                            const __half2* __restrict__ Wf,
                                            const float* __restrict__ bias,
                                            const __half2* __restrict__ W4f,
                                            int half,
                                            float* __restrict__ partsm) {
    constexpr int Ks = NH / 16;
    constexpr int Ks2 = Ks / 2;
    const int lane = threadIdx.x & 31;
    const int warp = threadIdx.x >> 5;
    const int g = lane >> 2;
    const int tg = lane & 3;
    const int ncol0 = warp * 64;

    uint32_t abase[2];
    {
        const __half* ap = A + (lane & 15) * HSTRIDE + ((lane >> 4) << 3);
#pragma unroll
        for (int rt = 0; rt < 2; rt++)
            abase[rt] = (uint32_t)__cvta_generic_to_shared(ap + rt * 16 * HSTRIDE);
    }

    const uint4* bq = reinterpret_cast<const uint4*>(Wf) + (warp * 8) * (Ks2 * 32) + lane;

    float c[2][8][4];
#pragma unroll
    for (int rt = 0; rt < 2; rt++)
#pragma unroll
        for (int nt = 0; nt < 8; nt++)
#pragma unroll
            for (int r = 0; r < 4; r++) c[rt][nt][r] = 0.f;

    uint4 bc[8];
#pragma unroll
    for (int nt = 0; nt < 8; nt++) bc[nt] = bq[nt * (Ks2 * 32)];

#pragma unroll 2
    for (int ks2 = 0; ks2 < Ks2; ks2++) {
        uint32_t a[2][4];
        ldsm4(a[0], abase[0] + (ks2 * 2) * 32);
        ldsm4(a[1], abase[1] + (ks2 * 2) * 32);
#pragma unroll
        for (int rt = 0; rt < 2; rt++)
#pragma unroll
            for (int nt = 0; nt < 8; nt++)
                mma_m16n8k16(c[rt][nt], a[rt], bc[nt].x, bc[nt].y);

        ldsm4(a[0], abase[0] + (ks2 * 2 + 1) * 32);
        ldsm4(a[1], abase[1] + (ks2 * 2 + 1) * 32);
#pragma unroll
        for (int nt = 0; nt < 8; nt++) {
            mma_m16n8k16(c[0][nt], a[0], bc[nt].z, bc[nt].w);
            mma_m16n8k16(c[1][nt], a[1], bc[nt].z, bc[nt].w);
            if (ks2 + 1 < Ks2)
                bc[nt] = bq[nt * (Ks2 * 32) + (ks2 + 1) * 32];
        }
    }

    // fused epilogue: tanh then dot with W4 fragments -> row partials
    const __half2* wb = W4f + warp * 2048 + lane;
    float part[2][2];
#pragma unroll
    for (int rt = 0; rt < 2; rt++) { part[rt][0] = 0.f; part[rt][1] = 0.f; }

#pragma unroll
    for (int nt = 0; nt < 8; nt++) {
        const int n0 = ncol0 + nt * 8 + tg * 2;
        const float2 bb = *reinterpret_cast<const float2*>(bias + n0);
#pragma unroll
        for (int rt = 0; rt < 2; rt++) {
            const int rtg = half * 2 + rt;     // global row tile
            const float t0 = tanh_approx(c[rt][nt][0] + bb.x);
            const float t1 = tanh_approx(c[rt][nt][1] + bb.y);
            const float t2 = tanh_approx(c[rt][nt][2] + bb.x);
            const float t3 = tanh_approx(c[rt][nt][3] + bb.y);
            const float2 wA = __half22float2(wb[((rtg * 8 + nt) * 2 + 0) * 32]);
            const float2 wB = __half22float2(wb[((rtg * 8 + nt) * 2 + 1) * 32]);
            part[rt][0] = fmaf(t0, wA.x, fmaf(t1, wA.y, part[rt][0]));
            part[rt][1] = fmaf(t2, wB.x, fmaf(t3, wB.y, part[rt][1]));
        }
    }

#pragma unroll
    for (int rt = 0; rt < 2; rt++) {
#pragma unroll
        for (int p = 0; p < 2; p++) {
            float v = part[rt][p];
            v += __shfl_xor_sync(0xFFFFFFFFu, v, 1);
            v += __shfl_xor_sync(0xFFFFFFFFu, v, 2);
            if (tg == 0) partsm[warp * MR + rt * 16 + p * 8 + g] = v;
        }
    }
}

__global__ __launch_bounds__(256, 2)
void decoder_kernel(const float* __restrict__ x, const float* __restrict__ koop,
                    const float* __restrict__ sb1, const float* __restrict__ sb2,
                    const float* __restrict__ sb3, const float* __restrict__ sb4,
                    const float* __restrict__ tb1, const float* __restrict__ tb2,
                    const float* __restrict__ tb3, const float* __restrict__ tb4,
                    float* __restrict__ out) {
    extern __shared__ __half smem[];
    __half* zs = smem;                 // 32 x 72
    __half* buf0 = smem + BUF0_OFF;    // 32 x 520
    __half* buf1 = smem + BUF1_OFF;    // 32 x 520
    float* partsm_s = reinterpret_cast<float*>(smem + SMEM_HALVES);  // 8 x 32
    float* partsm_t = partsm_s + 8 * MR;                             // 8 x 32

    const int b = blockIdx.x >> 1;
    const int half = blockIdx.x & 1;
    const float* kb = koop + b * (NL * ND);

    // Load + transpose z rows [half*32, half*32+32): zs[d_local][l] = koop[b][l][d]
    for (int i = threadIdx.x; i < NL * MR; i += 256) {
        const int l = i >> 5, dl = i & (MR - 1);
        zs[dl * ZSTRIDE + l] = __float2half_rn(kb[l * ND + half * MR + dl]);
    }
    __syncthreads();

    // ---- s MLP ----
    mlp_layer<NL, ZSTRIDE>(zs, g_Wf1[0], sb1, buf1);
    __syncthreads();
    mlp_layer<NH, HSTRIDE>(buf1, g_Wf2[0], sb2, buf0);
    __syncthreads();
    mlp_layer_diag(buf0, g_Wf3[0], sb3, g_W4f[0], half, partsm_s);
    // NO barrier: diag_s reads buf0/writes partsm_s; t-layer1 reads zs/writes
    // buf1 (last readers of buf1 were fenced by the barrier above). Warps that
    // finish diag_s's epilogue immediately start t-layer1 MMAs.

    // ---- t MLP ----
    mlp_layer<NL, ZSTRIDE>(zs, g_Wf1[1], tb1, buf1);
    __syncthreads();
    mlp_layer<NH, HSTRIDE>(buf1, g_Wf2[1], tb2, buf0);
    __syncthreads();
    mlp_layer_diag(buf0, g_Wf3[1], tb3, g_W4f[1], half, partsm_t);
    __syncthreads();

    // ---- combined tail: reduce both partials, produce output ----
    if (threadIdx.x < MR) {
        const int r = threadIdx.x;
        const int d = half * MR + r;
        float ss = 0.f, tt = 0.f;
#pragma unroll
        for (int w = 0; w < 8; w++) {
            ss += partsm_s[w * MR + r];
            tt += partsm_t[w * MR + r];
        }
        ss += sb4[d];
        tt += tb4[d];
        out[b * ND + d] = (x[b * ND + d] - tt) * __expf(-ss);
    }
}

extern "C" void kernel_launch(void* const* d_in, const int* in_sizes, int n_in,
                              void* d_out, int out_size) {
    (void)in_sizes; (void)n_in; (void)out_size;
    const float* x   = (const float*)d_in[0];
    const float* kp  = (const float*)d_in[1];
    const float* sW1 = (const float*)d_in[2];
    const float* sb1 = (const float*)d_in[3];
    const float* sW2 = (const float*)d_in[4];
    const float* sb2 = (const float*)d_in[5];
    const float* sW3 = (const float*)d_in[6];
    const float* sb3 = (const float*)d_in[7];
    const float* sW4 = (const float*)d_in[8];
    const float* sb4 = (const float*)d_in[9];
    const float* tW1 = (const float*)d_in[10];
    const float* tb1 = (const float*)d_in[11];
    const float* tW2 = (const float*)d_in[12];
    const float* tb2 = (const float*)d_in[13];
    const float* tW3 = (const float*)d_in[14];
    const float* tb3 = (const float*)d_in[15];
    const float* tW4 = (const float*)d_in[16];
    const float* tb4 = (const float*)d_in[17];
    float* out = (float*)d_out;

    convert_kernel<<<(NH * NH / 2 + 255) / 256, 256>>>(sW1, sW2, sW3, sW4, tW1, tW2, tW3, tW4);

    cudaFuncSetAttribute(decoder_kernel, cudaFuncAttributeMaxDynamicSharedMemorySize, SMEM_BYTES);
    decoder_kernel<<<NB * 2, 256, SMEM_BYTES>>>(x, kp,
                                                sb1, sb2, sb3, sb4,
                                                tb1, tb2, tb3, tb4,
                                                out);
}

// round 15
// speedup vs baseline: 1.4881x; 1.4881x over previous
#include <cuda_runtime.h>
#include <cuda_fp16.h>
#include <math.h>
#include <stdint.h>

// Problem sizes
#define NB 2048
#define ND 64
#define NL 64
#define NH 512
#define MR 32                 // rows per CTA (half a batch element)

// SMEM layout (in halves)
#define ZSTRIDE 72            // 64 + 8 pad -> conflict-free ldmatrix
#define HSTRIDE 520           // 512 + 8 pad
#define BUFA_OFF (MR * ZSTRIDE)
#define BUFB_OFF (BUFA_OFF + MR * HSTRIDE)
#define BUFC_OFF (BUFB_OFF + MR * HSTRIDE)
#define SMEM_HALVES (BUFC_OFF + MR * HSTRIDE)
// after halves: partsm_s[8*32] f32, partsm_t[8*32] f32
#define SMEM_BYTES (SMEM_HALVES * 2 + 16 * MR * 4 + 16)

// Fragment-major fp16 weights, PAIR-PACKED for LDG.128 (same layout as r12):
__device__ __half2 g_Wf1[2][NL * NH / 2];   // Ks = 4
__device__ __half2 g_Wf2[2][NH * NH / 2];   // Ks = 32
__device__ __half2 g_Wf3[2][NH * NH / 2];   // Ks = 32
// W4 packed to match mma accumulator layout:
// j = ((((w*4+rt)*8+nt)*2+p)*32+lane); half2(W4[n0][r], W4[n0+1][r]),
// n0 = w*64+nt*8+(lane&3)*2, r = rt*16+(lane>>2)+p*8   (rt GLOBAL 0..3, w 0..7)
__device__ __half2 g_W4f[2][ND * NH / 2];

__global__ void convert_kernel(const float* __restrict__ sW1, const float* __restrict__ sW2,
                               const float* __restrict__ sW3, const float* __restrict__ sW4,
                               const float* __restrict__ tW1, const float* __restrict__ tW2,
                               const float* __restrict__ tW3, const float* __restrict__ tW4) {
    const int i = blockIdx.x * blockDim.x + threadIdx.x;
    const float* w1[2] = {sW1, tW1};
    const float* w2[2] = {sW2, tW2};
    const float* w3[2] = {sW3, tW3};
    const float* w4[2] = {sW4, tW4};
#pragma unroll
    for (int m = 0; m < 2; m++) {
        if (i < NH * NH / 2) {   // W2/W3: Ks = 32, Ks2 = 16
            const int c = i & 3, w = c & 1, sub = c >> 1;
            const int lane = (i >> 2) & 31, ks2 = (i >> 7) & 15, n8 = i >> 11;
            const int kstep = ks2 * 2 + sub;
            const int n = n8 * 8 + (lane >> 2);
            const int k = kstep * 16 + (lane & 3) * 2 + w * 8;
            g_Wf2[m][i] = __floats2half2_rn(w2[m][k * NH + n], w2[m][(k + 1) * NH + n]);
            g_Wf3[m][i] = __floats2half2_rn(w3[m][k * NH + n], w3[m][(k + 1) * NH + n]);
        }
        if (i < NL * NH / 2) {   // W1: Ks = 4, Ks2 = 2
            const int c = i & 3, w = c & 1, sub = c >> 1;
            const int lane = (i >> 2) & 31, ks2 = (i >> 7) & 1, n8 = i >> 8;
            const int kstep = ks2 * 2 + sub;
            const int n = n8 * 8 + (lane >> 2);
            const int k = kstep * 16 + (lane & 3) * 2 + w * 8;
            g_Wf1[m][i] = __floats2half2_rn(w1[m][k * NH + n], w1[m][(k + 1) * NH + n]);
        }
        if (i < ND * NH / 2) {   // W4 (512,64) -> accumulator-matched fragments
            const int lane = i & 31, p = (i >> 5) & 1, nt = (i >> 6) & 7;
            const int rt = (i >> 9) & 3, w = i >> 11;
            const int tg = lane & 3, g = lane >> 2;
            const int n0 = w * 64 + nt * 8 + tg * 2;
            const int r = rt * 16 + g + p * 8;
            g_W4f[m][i] = __floats2half2_rn(w4[m][n0 * ND + r], w4[m][(n0 + 1) * ND + r]);
        }
    }
}

__device__ __forceinline__ float tanh_approx(float x) {
    float y;
    asm("tanh.approx.f32 %0, %1;" : "=f"(y) : "f"(x));
    return y;
}

__device__ __forceinline__ void mma_m16n8k16(float c[4], const uint32_t a[4],
                                             uint32_t b0, uint32_t b1) {
    asm volatile(
        "mma.sync.aligned.m16n8k16.row.col.f32.f16.f16.f32 "
        "{%0,%1,%2,%3}, {%4,%5,%6,%7}, {%8,%9}, {%0,%1,%2,%3};\n"
        : "+f"(c[0]), "+f"(c[1]), "+f"(c[2]), "+f"(c[3])
        : "r"(a[0]), "r"(a[1]), "r"(a[2]), "r"(a[3]), "r"(b0), "r"(b1));
}

__device__ __forceinline__ void ldsm4(uint32_t a[4], uint32_t addr) {
    asm volatile("ldmatrix.sync.aligned.m8n8.x4.shared.b16 {%0,%1,%2,%3}, [%4];"
                 : "=r"(a[0]), "=r"(a[1]), "=r"(a[2]), "=r"(a[3]) : "r"(addr));
}

// One dense layer: Out(32 x 512) = tanh(A(32 x K) @ W(K x 512) + bias)
// 8 warps; warp w owns output columns [w*64, w*64+64); 2 row tiles (M=32).
// EXACT r12 inner loop (loop-top B loads, unroll 2).
template <int K, int AS>
__device__ __noinline__ void mlp_layer(const __half* __restrict__ A,
                                       const __half2* __restrict__ Wf,
                                       const float* __restrict__ bias,
                                       __half* __restrict__ Out) {
    constexpr int Ks = K / 16;
    constexpr int Ks2 = Ks / 2;
    const int lane = threadIdx.x & 31;
    const int warp = threadIdx.x >> 5;
    const int g = lane >> 2;
    const int tg = lane & 3;
    const int ncol0 = warp * 64;

    uint32_t abase[2];
    {
        const __half* ap = A + (lane & 15) * AS + ((lane >> 4) << 3);
#pragma unroll
        for (int rt = 0; rt < 2; rt++)
            abase[rt] = (uint32_t)__cvta_generic_to_shared(ap + rt * 16 * AS);
    }

    const uint4* bq = reinterpret_cast<const uint4*>(Wf) + (warp * 8) * (Ks2 * 32) + lane;

    float c[2][8][4];
#pragma unroll
    for (int rt = 0; rt < 2; rt++)
#pragma unroll
        for (int nt = 0; nt < 8; nt++)
#pragma unroll
            for (int r = 0; r < 4; r++) c[rt][nt][r] = 0.f;

#pragma unroll 2
    for (int ks2 = 0; ks2 < Ks2; ks2++) {
        uint4 bc[8];
#pragma unroll
        for (int nt = 0; nt < 8; nt++) bc[nt] = bq[nt * (Ks2 * 32) + ks2 * 32];

        uint32_t a[2][4];
#pragma unroll
        for (int rt = 0; rt < 2; rt++) ldsm4(a[rt], abase[rt] + (ks2 * 2) * 32);
#pragma unroll
        for (int rt = 0; rt < 2; rt++)
#pragma unroll
            for (int nt = 0; nt < 8; nt++)
                mma_m16n8k16(c[rt][nt], a[rt], bc[nt].x, bc[nt].y);

#pragma unroll
        for (int rt = 0; rt < 2; rt++) ldsm4(a[rt], abase[rt] + (ks2 * 2 + 1) * 32);
#pragma unroll
        for (int rt = 0; rt < 2; rt++)
#pragma unroll
            for (int nt = 0; nt < 8; nt++)
                mma_m16n8k16(c[rt][nt], a[rt], bc[nt].z, bc[nt].w);
    }

    // epilogue: + bias, tanh, pack to half2, store
#pragma unroll
    for (int nt = 0; nt < 8; nt++) {
        const int n0 = ncol0 + nt * 8 + tg * 2;
        const float2 bb = *reinterpret_cast<const float2*>(bias + n0);
#pragma unroll
        for (int rt = 0; rt < 2; rt++) {
            float v0 = tanh_approx(c[rt][nt][0] + bb.x);
            float v1 = tanh_approx(c[rt][nt][1] + bb.y);
            float v2 = tanh_approx(c[rt][nt][2] + bb.x);
            float v3 = tanh_approx(c[rt][nt][3] + bb.y);
            *reinterpret_cast<__half2*>(Out + (rt * 16 + g) * HSTRIDE + n0) =
                __floats2half2_rn(v0, v1);
            *reinterpret_cast<__half2*>(Out + (rt * 16 + g + 8) * HSTRIDE + n0) =
                __floats2half2_rn(v2, v3);
        }
    }
}

// Layer 3 fused with the layer-4 diagonal (M=32; global row = half*32 + local).
__device__ __noinline__ void mlp_layer_diag(const __half* __restrict__ A,
                                            const __half2* __restrict__ Wf,
                                            const float* __restrict__ bias,
                                            const __half2* __restrict__ W4f,
                                            int half,
                                            float* __restrict__ partsm) {
    constexpr int Ks = NH / 16;
    constexpr int Ks2 = Ks / 2;
    const int lane = threadIdx.x & 31;
    const int warp = threadIdx.x >> 5;
    const int g = lane >> 2;
    const int tg = lane & 3;
    const int ncol0 = warp * 64;

    uint32_t abase[2];
    {
        const __half* ap = A + (lane & 15) * HSTRIDE + ((lane >> 4) << 3);
#pragma unroll
        for (int rt = 0; rt < 2; rt++)
            abase[rt] = (uint32_t)__cvta_generic_to_shared(ap + rt * 16 * HSTRIDE);
    }

    const uint4* bq = reinterpret_cast<const uint4*>(Wf) + (warp * 8) * (Ks2 * 32) + lane;

    float c[2][8][4];
#pragma unroll
    for (int rt = 0; rt < 2; rt++)
#pragma unroll
        for (int nt = 0; nt < 8; nt++)
#pragma unroll
            for (int r = 0; r < 4; r++) c[rt][nt][r] = 0.f;

#pragma unroll 2
    for (int ks2 = 0; ks2 < Ks2; ks2++) {
        uint4 bc[8];
#pragma unroll
        for (int nt = 0; nt < 8; nt++) bc[nt] = bq[nt * (Ks2 * 32) + ks2 * 32];

        uint32_t a[2][4];
#pragma unroll
        for (int rt = 0; rt < 2; rt++) ldsm4(a[rt], abase[rt] + (ks2 * 2) * 32);
#pragma unroll
        for (int rt = 0; rt < 2; rt++)
#pragma unroll
            for (int nt = 0; nt < 8; nt++)
                mma_m16n8k16(c[rt][nt], a[rt], bc[nt].x, bc[nt].y);

#pragma unroll
        for (int rt = 0; rt < 2; rt++) ldsm4(a[rt], abase[rt] + (ks2 * 2 + 1) * 32);
#pragma unroll
        for (int rt = 0; rt < 2; rt++)
#pragma unroll
            for (int nt = 0; nt < 8; nt++)
                mma_m16n8k16(c[rt][nt], a[rt], bc[nt].z, bc[nt].w);
    }

    // fused epilogue: tanh then dot with W4 fragments -> row partials
    const __half2* wb = W4f + warp * 2048 + lane;
    float part[2][2];
#pragma unroll
    for (int rt = 0; rt < 2; rt++) { part[rt][0] = 0.f; part[rt][1] = 0.f; }

#pragma unroll
    for (int nt = 0; nt < 8; nt++) {
        const int n0 = ncol0 + nt * 8 + tg * 2;
        const float2 bb = *reinterpret_cast<const float2*>(bias + n0);
#pragma unroll
        for (int rt = 0; rt < 2; rt++) {
            const int rtg = half * 2 + rt;     // global row tile
            const float t0 = tanh_approx(c[rt][nt][0] + bb.x);
            const float t1 = tanh_approx(c[rt][nt][1] + bb.y);
            const float t2 = tanh_approx(c[rt][nt][2] + bb.x);
            const float t3 = tanh_approx(c[rt][nt][3] + bb.y);
            const float2 wA = __half22float2(wb[((rtg * 8 + nt) * 2 + 0) * 32]);
            const float2 wB = __half22float2(wb[((rtg * 8 + nt) * 2 + 1) * 32]);
            part[rt][0] = fmaf(t0, wA.x, fmaf(t1, wA.y, part[rt][0]));
            part[rt][1] = fmaf(t2, wB.x, fmaf(t3, wB.y, part[rt][1]));
        }
    }

#pragma unroll
    for (int rt = 0; rt < 2; rt++) {
#pragma unroll
        for (int p = 0; p < 2; p++) {
            float v = part[rt][p];
            v += __shfl_xor_sync(0xFFFFFFFFu, v, 1);
            v += __shfl_xor_sync(0xFFFFFFFFu, v, 2);
            if (tg == 0) partsm[warp * MR + rt * 16 + p * 8 + g] = v;
        }
    }
}

__global__ __launch_bounds__(256, 2)
void decoder_kernel(const float* __restrict__ x, const float* __restrict__ koop,
                    const float* __restrict__ sb1, const float* __restrict__ sb2,
                    const float* __restrict__ sb3, const float* __restrict__ sb4,
                    const float* __restrict__ tb1, const float* __restrict__ tb2,
                    const float* __restrict__ tb3, const float* __restrict__ tb4,
                    float* __restrict__ out) {
    extern __shared__ __half smem[];
    __half* zs = smem;                  // 32 x 72
    __half* bufA = smem + BUFA_OFF;     // 32 x 520
    __half* bufB = smem + BUFB_OFF;     // 32 x 520
    __half* bufC = smem + BUFC_OFF;     // 32 x 520
    float* partsm_s = reinterpret_cast<float*>(smem + SMEM_HALVES);  // 8 x 32
    float* partsm_t = partsm_s + 8 * MR;                             // 8 x 32

    const int b = blockIdx.x >> 1;
    const int half = blockIdx.x & 1;
    const float* kb = koop + b * (NL * ND);

    // Phase 1: load + transpose z rows [half*32, half*32+32)
    for (int i = threadIdx.x; i < NL * MR; i += 256) {
        const int l = i >> 5, dl = i & (MR - 1);
        zs[dl * ZSTRIDE + l] = __float2half_rn(kb[l * ND + half * MR + dl]);
    }
    __syncthreads();

    // Phase 2: s-l1 (z->A) and t-l1 (z->B) — independent, one barrier.
    mlp_layer<NL, ZSTRIDE>(zs, g_Wf1[0], sb1, bufA);
    mlp_layer<NL, ZSTRIDE>(zs, g_Wf1[1], tb1, bufB);
    __syncthreads();

    // Phase 3: s-l2 (A->C).
    mlp_layer<NH, HSTRIDE>(bufA, g_Wf2[0], sb2, bufC);
    __syncthreads();

    // Phase 4: t-l2 (B->A) and s-diag (C->partsS).
    // A's last reader (s-l2) finished at barrier 3; C was written before it.
    mlp_layer<NH, HSTRIDE>(bufB, g_Wf2[1], tb2, bufA);
    mlp_layer_diag(bufC, g_Wf3[0], sb3, g_W4f[0], half, partsm_s);
    __syncthreads();

    // Phase 5: t-diag (A->partsT).
    mlp_layer_diag(bufA, g_Wf3[1], tb3, g_W4f[1], half, partsm_t);
    __syncthreads();

    // Combined tail: reduce both partials, produce output.
    if (threadIdx.x < MR) {
        const int r = threadIdx.x;
        const int d = half * MR + r;
        float ss = 0.f, tt = 0.f;
#pragma unroll
        for (int w = 0; w < 8; w++) {
            ss += partsm_s[w * MR + r];
            tt += partsm_t[w * MR + r];
        }
        ss += sb4[d];
        tt += tb4[d];
        out[b * ND + d] = (x[b * ND + d] - tt) * __expf(-ss);
    }
}

extern "C" void kernel_launch(void* const* d_in, const int* in_sizes, int n_in,
                              void* d_out, int out_size) {
    (void)in_sizes; (void)n_in; (void)out_size;
    const float* x   = (const float*)d_in[0];
    const float* kp  = (const float*)d_in[1];
    const float* sW1 = (const float*)d_in[2];
    const float* sb1 = (const float*)d_in[3];
    const float* sW2 = (const float*)d_in[4];
    const float* sb2 = (const float*)d_in[5];
    const float* sW3 = (const float*)d_in[6];
    const float* sb3 = (const float*)d_in[7];
    const float* sW4 = (const float*)d_in[8];
    const float* sb4 = (const float*)d_in[9];
    const float* tW1 = (const float*)d_in[10];
    const float* tb1 = (const float*)d_in[11];
    const float* tW2 = (const float*)d_in[12];
    const float* tb2 = (const float*)d_in[13];
    const float* tW3 = (const float*)d_in[14];
    const float* tb3 = (const float*)d_in[15];
    const float* tW4 = (const float*)d_in[16];
    const float* tb4 = (const float*)d_in[17];
    float* out = (float*)d_out;

    convert_kernel<<<(NH * NH / 2 + 255) / 256, 256>>>(sW1, sW2, sW3, sW4, tW1, tW2, tW3, tW4);

    cudaFuncSetAttribute(decoder_kernel, cudaFuncAttributeMaxDynamicSharedMemorySize, SMEM_BYTES);
    decoder_kernel<<<NB * 2, 256, SMEM_BYTES>>>(x, kp,
                                                sb1, sb2, sb3, sb4,
                                                tb1, tb2, tb3, tb4,
                                                out);
}